// round 11
// baseline (speedup 1.0000x reference)
#include <cuda_runtime.h>
#include <cuda_fp16.h>
#include <cstdint>

// Problem constants
#define T_DIM 4096
#define K_DIM 4096
#define N_DIM 11008
#define KPACK (K_DIM / 2)

constexpr int BM = 128;
constexpr int BN = 128;
constexpr int BK = 128;             // int8 K elements per stage (128 B per row)
constexpr int THREADS = 256;
constexpr int SSTRIDE = 36;         // words per row: 32 data (128 int8) + 4 pad
constexpr int STAGE_WORDS = BM * SSTRIDE;      // 4608 words = 18432 B per operand
constexpr int STAGES = 3;
constexpr int B_BASE = STAGES * STAGE_WORDS;
constexpr int SMEM_WORDS = 2 * STAGES * STAGE_WORDS;   // 110592 B
constexpr int NUM_KB = K_DIM / BK;  // 32

// Static scratch: planar int8 operands (sign-extended nibbles), converted once.
__device__ int8_t g_a[(size_t)T_DIM * K_DIM];   // 16.8 MB
__device__ int8_t g_w[(size_t)N_DIM * K_DIM];   // 45.1 MB

// ---------------------------------------------------------------------------
// Repack: 4 int32 (one packed int4-pair byte each) -> 8 planar int8 (uint2 store).
// Nibble sign-extension via (x ^ 8) - 8 per byte lane (__vsub4).
__global__ void repack_s8_kernel(const int* __restrict__ src,
                                 uint2* __restrict__ dst, int n4) {
    int idx = blockIdx.x * blockDim.x + threadIdx.x;
    if (idx >= n4) return;
    uint4 w = reinterpret_cast<const uint4*>(src)[idx];
    unsigned t01 = __byte_perm(w.x, w.y, 0x0040);
    unsigned t23 = __byte_perm(w.z, w.w, 0x4000);
    unsigned x   = __byte_perm(t01, t23, 0x7610);      // 4 packed bytes
    unsigned lo = x & 0x0F0F0F0Fu;
    unsigned hi = (x >> 4) & 0x0F0F0F0Fu;
    lo = __vsub4(lo ^ 0x08080808u, 0x08080808u);
    hi = __vsub4(hi ^ 0x08080808u, 0x08080808u);
    uint2 o;
    o.x = __byte_perm(lo, hi, 0x5140);   // k: b0.lo, b0.hi, b1.lo, b1.hi
    o.y = __byte_perm(lo, hi, 0x7362);   // k: b2.lo, b2.hi, b3.lo, b3.hi
    dst[idx] = o;
}

// ---------------------------------------------------------------------------
__device__ __forceinline__ uint32_t smem_u32(const void* p) {
    uint32_t a;
    asm("{ .reg .u64 t; cvta.to.shared.u64 t, %1; cvt.u32.u64 %0, t; }" : "=r"(a) : "l"(p));
    return a;
}
__device__ __forceinline__ void cp_async16(uint32_t dst, const void* src) {
    asm volatile("cp.async.cg.shared.global [%0], [%1], 16;\n" :: "r"(dst), "l"(src));
}
#define CP_COMMIT() asm volatile("cp.async.commit_group;" ::: "memory")
#define CP_WAIT(n)  asm volatile("cp.async.wait_group %0;" :: "n"(n) : "memory")

__device__ __forceinline__ float h16(float v) {
    return __half2float(__float2half_rn(v));
}

__global__ void __launch_bounds__(THREADS, 2)
gemm_imma_pipe_kernel(const int8_t* __restrict__ A,
                      const float*  __restrict__ sx,
                      const int8_t* __restrict__ W,
                      const float*  __restrict__ ws,
                      float*        __restrict__ out) {
    extern __shared__ unsigned smem[];
    const uint32_t sb = smem_u32(smem);

    const int tid  = threadIdx.x;
    const int lane = tid & 31;
    const int warp = tid >> 5;
    const int tig  = lane & 3;
    const int grp  = lane >> 2;
    const int warpRow = (warp >> 2) * 64;
    const int warpCol = (warp & 3) * 32;
    const int bm = blockIdx.y * BM;
    const int bn = blockIdx.x * BN;

    int acc[4][4][4];
#pragma unroll
    for (int i = 0; i < 4; i++)
#pragma unroll
        for (int j = 0; j < 4; j++)
#pragma unroll
            for (int r = 0; r < 4; r++) acc[i][j][r] = 0;

    // cp.async loader: 1024 x 16B chunks per operand per stage; 4 per thread.
    const int seg  = tid & 7;        // 16B segment within the 128B K-slice
    const int row0 = tid >> 3;       // 0..31; rows row0 + 32*i
    const char* aG = (const char*)A + (size_t)(bm + row0) * K_DIM + (size_t)seg * 16;
    const char* bG = (const char*)W + (size_t)(bn + row0) * K_DIM + (size_t)seg * 16;
    uint32_t a_off[4], b_off[4];
#pragma unroll
    for (int i = 0; i < 4; i++) {
        a_off[i] = ((row0 + i * 32) * SSTRIDE + seg * 4) * 4;             // bytes
        b_off[i] = (B_BASE + (row0 + i * 32) * SSTRIDE + seg * 4) * 4;
    }

    auto load_stage = [&](int kb, int buf) {
        const size_t koff = (size_t)kb * BK;    // 128 B of K per stage
        const uint32_t sbase = sb + buf * (STAGE_WORDS * 4);
#pragma unroll
        for (int i = 0; i < 4; i++)
            cp_async16(sbase + a_off[i], aG + (size_t)(i * 32) * K_DIM + koff);
#pragma unroll
        for (int i = 0; i < 4; i++)
            cp_async16(sbase + b_off[i], bG + (size_t)(i * 32) * K_DIM + koff);
        CP_COMMIT();
    };

    load_stage(0, 0);
    load_stage(1, 1);

    for (int kb = 0; kb < NUM_KB; kb++) {
        if (kb + 2 < NUM_KB) load_stage(kb + 2, (kb + 2) % STAGES);
        const int rem = NUM_KB - 1 - kb;
        if (rem >= 2)      CP_WAIT(2);
        else if (rem == 1) CP_WAIT(1);
        else               CP_WAIT(0);
        __syncthreads();

        const unsigned* As = smem + (kb % STAGES) * STAGE_WORDS;
        const unsigned* Bs = As + B_BASE;

#pragma unroll
        for (int ks = 0; ks < 4; ks++) {   // four k32 steps per BK=128
            unsigned a[4][4];
            unsigned b[4][2];
#pragma unroll
            for (int mi = 0; mi < 4; mi++) {
                const int r0 = warpRow + mi * 16 + grp;
                const unsigned* p = As + r0 * SSTRIDE + ks * 8 + tig;
                a[mi][0] = p[0];                    // k[32ks+4tig..+3],   row r0
                a[mi][1] = p[8 * SSTRIDE];          //                     row r0+8
                a[mi][2] = p[4];                    // k[32ks+16+4tig..],  row r0
                a[mi][3] = p[8 * SSTRIDE + 4];      //                     row r0+8
            }
#pragma unroll
            for (int ni = 0; ni < 4; ni++) {
                const int c0 = warpCol + ni * 8 + grp;
                const unsigned* p = Bs + c0 * SSTRIDE + ks * 8 + tig;
                b[ni][0] = p[0];
                b[ni][1] = p[4];
            }
#pragma unroll
            for (int mi = 0; mi < 4; mi++) {
#pragma unroll
                for (int ni = 0; ni < 4; ni++) {
                    asm volatile(
                        "mma.sync.aligned.m16n8k32.row.col.s32.s8.s8.s32 "
                        "{%0,%1,%2,%3}, {%4,%5,%6,%7}, {%8,%9}, {%0,%1,%2,%3};\n"
                        : "+r"(acc[mi][ni][0]), "+r"(acc[mi][ni][1]),
                          "+r"(acc[mi][ni][2]), "+r"(acc[mi][ni][3])
                        : "r"(a[mi][0]), "r"(a[mi][1]), "r"(a[mi][2]), "r"(a[mi][3]),
                          "r"(b[ni][0]), "r"(b[ni][1]));
                }
            }
        }
        __syncthreads();
    }

    // Epilogue: int -> float, fused dequant, fp16-round, fp32 stores.
#pragma unroll
    for (int mi = 0; mi < 4; mi++) {
        const int r0 = bm + warpRow + mi * 16 + grp;
        const float s0 = sx[r0];
        const float s1 = sx[r0 + 8];
#pragma unroll
        for (int ni = 0; ni < 4; ni++) {
            const int c = bn + warpCol + ni * 8 + (tig << 1);
            const float w0 = ws[c];
            const float w1 = ws[c + 1];
            float2 v0 = make_float2(h16((float)acc[mi][ni][0] * s0 * w0),
                                    h16((float)acc[mi][ni][1] * s0 * w1));
            float2 v1 = make_float2(h16((float)acc[mi][ni][2] * s1 * w0),
                                    h16((float)acc[mi][ni][3] * s1 * w1));
            *reinterpret_cast<float2*>(out + (size_t)r0 * N_DIM + c)       = v0;
            *reinterpret_cast<float2*>(out + (size_t)(r0 + 8) * N_DIM + c) = v1;
        }
    }
}

// ---------------------------------------------------------------------------
extern "C" void kernel_launch(void* const* d_in, const int* in_sizes, int n_in,
                              void* d_out, int out_size) {
    // Resolve inputs BY ELEMENT COUNT (pairwise distinct; int8 arrives as int32).
    const int* pqx32 = nullptr;
    const int* wq32  = nullptr;
    const float* sx  = nullptr;
    const float* ws  = nullptr;
    for (int i = 0; i < n_in; i++) {
        long long s = (long long)in_sizes[i];
        if      (s == (long long)T_DIM * KPACK) pqx32 = (const int*)d_in[i];
        else if (s == (long long)N_DIM * KPACK) wq32  = (const int*)d_in[i];
        else if (s == (long long)T_DIM)         sx    = (const float*)d_in[i];
        else if (s == (long long)N_DIM)         ws    = (const float*)d_in[i];
    }
    if (!pqx32 || !wq32 || !sx || !ws) {
        pqx32 = (const int*)d_in[0];
        sx    = (const float*)d_in[1];
        wq32  = (const int*)d_in[2];
        ws    = (const float*)d_in[3];
    }
    float* out = (float*)d_out;

    int8_t* a_dev = nullptr;
    int8_t* w_dev = nullptr;
    cudaGetSymbolAddress((void**)&a_dev, g_a);
    cudaGetSymbolAddress((void**)&w_dev, g_w);

    // Prologue: int4 (delivered as int32) -> planar int8, once per element.
    const int n4_a = (T_DIM * KPACK) / 4;   // 2,097,152 -> grid 8192
    const int n4_b = (N_DIM * KPACK) / 4;   // 5,636,096 -> grid 22016
    repack_s8_kernel<<<n4_a / 256, 256>>>(pqx32, (uint2*)a_dev, n4_a);
    repack_s8_kernel<<<n4_b / 256, 256>>>(wq32,  (uint2*)w_dev, n4_b);

    cudaFuncSetAttribute(gemm_imma_pipe_kernel,
                         cudaFuncAttributeMaxDynamicSharedMemorySize,
                         SMEM_WORDS * 4);
    dim3 grid(N_DIM / BN, T_DIM / BM);   // 86 x 32
    gemm_imma_pipe_kernel<<<grid, THREADS, SMEM_WORDS * 4>>>(a_dev, sx, w_dev, ws, out);
}

// round 15
// speedup vs baseline: 1.8887x; 1.8887x over previous
#include <cuda_runtime.h>
#include <cuda_fp16.h>
#include <cstdint>

// Problem constants
#define T_DIM 4096
#define K_DIM 4096
#define N_DIM 11008
#define KPACK (K_DIM / 2)

constexpr int BM = 128;
constexpr int BN = 128;
constexpr int BK = 64;              // fp16 K elements per stage
constexpr int THREADS = 256;
constexpr int SSTRIDE = 36;         // words per row: 32 data (64 fp16) + 4 pad
constexpr int STAGE_WORDS = BM * SSTRIDE;      // 4608 words = 18432 B per operand
constexpr int STAGES = 3;
constexpr int B_BASE = STAGES * STAGE_WORDS;
constexpr int SMEM_WORDS = 2 * STAGES * STAGE_WORDS;   // 110592 B
constexpr int NUM_KB = K_DIM / BK;  // 64

// Static scratch: planar fp16 operands (values -7..7 exact), converted once.
__device__ __half g_a[(size_t)T_DIM * K_DIM];   // 32 MB
__device__ __half g_w[(size_t)N_DIM * K_DIM];   // 88 MB

// ---------------------------------------------------------------------------
// Repack: 4 int32 (one packed int4-pair byte each) -> 8 planar fp16.
// nibble n: m = n^8 in [0,15]; fp16 bits (0x6400|m) == 1024+m exactly; -1032 -> n.
__global__ void repack_fp16_kernel(const int* __restrict__ src,
                                   unsigned* __restrict__ dst, int n4) {
    int idx = blockIdx.x * blockDim.x + threadIdx.x;
    if (idx >= n4) return;
    uint4 w = reinterpret_cast<const uint4*>(src)[idx];
    unsigned t01 = __byte_perm(w.x, w.y, 0x0040);
    unsigned t23 = __byte_perm(w.z, w.w, 0x4000);
    unsigned x   = __byte_perm(t01, t23, 0x7610) ^ 0x88888888u;
    const unsigned MG = 0x64006400u;
    const __half2 bias = __float2half2_rn(1032.0f);
    unsigned u0 = ( x        & 0xFu) | ((x << 12) & 0x000F0000u) | MG;
    unsigned u1 = ((x >>  8) & 0xFu) | ((x <<  4) & 0x000F0000u) | MG;
    unsigned u2 = ((x >> 16) & 0xFu) | ((x >>  4) & 0x000F0000u) | MG;
    unsigned u3 = ((x >> 24) & 0xFu) | ((x >> 12) & 0x000F0000u) | MG;
    __half2 r0 = __hsub2(*reinterpret_cast<__half2*>(&u0), bias);
    __half2 r1 = __hsub2(*reinterpret_cast<__half2*>(&u1), bias);
    __half2 r2 = __hsub2(*reinterpret_cast<__half2*>(&u2), bias);
    __half2 r3 = __hsub2(*reinterpret_cast<__half2*>(&u3), bias);
    uint4 o;
    o.x = *reinterpret_cast<unsigned*>(&r0);
    o.y = *reinterpret_cast<unsigned*>(&r1);
    o.z = *reinterpret_cast<unsigned*>(&r2);
    o.w = *reinterpret_cast<unsigned*>(&r3);
    reinterpret_cast<uint4*>(dst)[idx] = o;
}

// ---------------------------------------------------------------------------
__device__ __forceinline__ uint32_t smem_u32(const void* p) {
    uint32_t a;
    asm("{ .reg .u64 t; cvta.to.shared.u64 t, %1; cvt.u32.u64 %0, t; }" : "=r"(a) : "l"(p));
    return a;
}
__device__ __forceinline__ void cp_async16(uint32_t dst, const void* src) {
    asm volatile("cp.async.cg.shared.global [%0], [%1], 16;\n" :: "r"(dst), "l"(src));
}
#define CP_COMMIT() asm volatile("cp.async.commit_group;" ::: "memory")
#define CP_WAIT(n)  asm volatile("cp.async.wait_group %0;" :: "n"(n) : "memory")

__device__ __forceinline__ float h16(float v) {
    return __half2float(__float2half_rn(v));
}

__global__ void __launch_bounds__(THREADS, 2)
gemm_hmma16_pipe_kernel(const __half* __restrict__ A,
                        const float*  __restrict__ sx,
                        const __half* __restrict__ W,
                        const float*  __restrict__ ws,
                        float*        __restrict__ out) {
    extern __shared__ unsigned smem[];
    const uint32_t sb = smem_u32(smem);

    const int tid  = threadIdx.x;
    const int lane = tid & 31;
    const int warp = tid >> 5;
    const int tig  = lane & 3;
    const int grp  = lane >> 2;
    const int warpRow = (warp >> 2) * 64;
    const int warpCol = (warp & 3) * 32;
    const int bm = blockIdx.y * BM;
    const int bn = blockIdx.x * BN;

    float acc[4][4][4];
#pragma unroll
    for (int i = 0; i < 4; i++)
#pragma unroll
        for (int j = 0; j < 4; j++)
#pragma unroll
            for (int r = 0; r < 4; r++) acc[i][j][r] = 0.0f;

    // cp.async loader: 1024 x 16B chunks per operand per stage; 4 per thread.
    const int seg  = tid & 7;
    const int row0 = tid >> 3;       // 0..31; rows row0 + 32*i
    const char* aG = (const char*)A + ((size_t)(bm + row0) * K_DIM + (size_t)seg * 8) * 2;
    const char* bG = (const char*)W + ((size_t)(bn + row0) * K_DIM + (size_t)seg * 8) * 2;
    uint32_t a_off[4], b_off[4];
#pragma unroll
    for (int i = 0; i < 4; i++) {
        a_off[i] = ((row0 + i * 32) * SSTRIDE + seg * 4) * 4;             // bytes
        b_off[i] = (B_BASE + (row0 + i * 32) * SSTRIDE + seg * 4) * 4;
    }

    auto load_stage = [&](int kb, int buf) {
        const size_t koff = (size_t)kb * (BK * 2);   // 128 B of K per stage
        const uint32_t sbase = sb + buf * (STAGE_WORDS * 4);
#pragma unroll
        for (int i = 0; i < 4; i++)
            cp_async16(sbase + a_off[i], aG + (size_t)(i * 32) * K_DIM * 2 + koff);
#pragma unroll
        for (int i = 0; i < 4; i++)
            cp_async16(sbase + b_off[i], bG + (size_t)(i * 32) * K_DIM * 2 + koff);
        CP_COMMIT();
    };

    load_stage(0, 0);
    load_stage(1, 1);

    for (int kb = 0; kb < NUM_KB; kb++) {
        if (kb + 2 < NUM_KB) load_stage(kb + 2, (kb + 2) % STAGES);
        const int rem = NUM_KB - 1 - kb;
        if (rem >= 2)      CP_WAIT(2);
        else if (rem == 1) CP_WAIT(1);
        else               CP_WAIT(0);
        __syncthreads();

        const unsigned* As = smem + (kb % STAGES) * STAGE_WORDS;
        const unsigned* Bs = As + B_BASE;

        // fp16x2 accumulators for the current k32 group (exact: |sum| <= 1568 < 2048)
        unsigned d[4][4][2];

#pragma unroll
        for (int ks = 0; ks < 4; ks++) {   // four k16 steps per BK=64
            unsigned a[4][4];
            unsigned b[4][2];
#pragma unroll
            for (int mi = 0; mi < 4; mi++) {
                const int r0 = warpRow + mi * 16 + grp;
                const unsigned* p = As + r0 * SSTRIDE + ks * 8 + tig;
                a[mi][0] = p[0];
                a[mi][1] = p[8 * SSTRIDE];
                a[mi][2] = p[4];
                a[mi][3] = p[8 * SSTRIDE + 4];
            }
#pragma unroll
            for (int ni = 0; ni < 4; ni++) {
                const int c0 = warpCol + ni * 8 + grp;
                const unsigned* p = Bs + c0 * SSTRIDE + ks * 8 + tig;
                b[ni][0] = p[0];
                b[ni][1] = p[4];
            }
            if ((ks & 1) == 0) {
                // start fp16 partial: D = A*B + 0
                const unsigned z = 0u;
#pragma unroll
                for (int mi = 0; mi < 4; mi++)
#pragma unroll
                    for (int ni = 0; ni < 4; ni++) {
                        asm volatile(
                            "mma.sync.aligned.m16n8k16.row.col.f16.f16.f16.f16 "
                            "{%0,%1}, {%2,%3,%4,%5}, {%6,%7}, {%8,%9};\n"
                            : "=r"(d[mi][ni][0]), "=r"(d[mi][ni][1])
                            : "r"(a[mi][0]), "r"(a[mi][1]), "r"(a[mi][2]), "r"(a[mi][3]),
                              "r"(b[ni][0]), "r"(b[ni][1]), "r"(z), "r"(z));
                    }
            } else {
                // chain into fp16 partial, then drain to fp32
#pragma unroll
                for (int mi = 0; mi < 4; mi++)
#pragma unroll
                    for (int ni = 0; ni < 4; ni++) {
                        asm volatile(
                            "mma.sync.aligned.m16n8k16.row.col.f16.f16.f16.f16 "
                            "{%0,%1}, {%2,%3,%4,%5}, {%6,%7}, {%0,%1};\n"
                            : "+r"(d[mi][ni][0]), "+r"(d[mi][ni][1])
                            : "r"(a[mi][0]), "r"(a[mi][1]), "r"(a[mi][2]), "r"(a[mi][3]),
                              "r"(b[ni][0]), "r"(b[ni][1]));
                    }
#pragma unroll
                for (int mi = 0; mi < 4; mi++)
#pragma unroll
                    for (int ni = 0; ni < 4; ni++) {
                        float2 lo = __half22float2(*reinterpret_cast<__half2*>(&d[mi][ni][0]));
                        float2 hi = __half22float2(*reinterpret_cast<__half2*>(&d[mi][ni][1]));
                        acc[mi][ni][0] += lo.x;
                        acc[mi][ni][1] += lo.y;
                        acc[mi][ni][2] += hi.x;
                        acc[mi][ni][3] += hi.y;
                    }
            }
        }
        __syncthreads();
    }

    // Epilogue: fused dequant, fp16-round, fp32 stores.
#pragma unroll
    for (int mi = 0; mi < 4; mi++) {
        const int r0 = bm + warpRow + mi * 16 + grp;
        const float s0 = sx[r0];
        const float s1 = sx[r0 + 8];
#pragma unroll
        for (int ni = 0; ni < 4; ni++) {
            const int c = bn + warpCol + ni * 8 + (tig << 1);
            const float w0 = ws[c];
            const float w1 = ws[c + 1];
            float2 v0 = make_float2(h16(acc[mi][ni][0] * s0 * w0),
                                    h16(acc[mi][ni][1] * s0 * w1));
            float2 v1 = make_float2(h16(acc[mi][ni][2] * s1 * w0),
                                    h16(acc[mi][ni][3] * s1 * w1));
            *reinterpret_cast<float2*>(out + (size_t)r0 * N_DIM + c)       = v0;
            *reinterpret_cast<float2*>(out + (size_t)(r0 + 8) * N_DIM + c) = v1;
        }
    }
}

// ---------------------------------------------------------------------------
extern "C" void kernel_launch(void* const* d_in, const int* in_sizes, int n_in,
                              void* d_out, int out_size) {
    // Resolve inputs BY ELEMENT COUNT (pairwise distinct; int8 arrives as int32).
    const int* pqx32 = nullptr;
    const int* wq32  = nullptr;
    const float* sx  = nullptr;
    const float* ws  = nullptr;
    for (int i = 0; i < n_in; i++) {
        long long s = (long long)in_sizes[i];
        if      (s == (long long)T_DIM * KPACK) pqx32 = (const int*)d_in[i];
        else if (s == (long long)N_DIM * KPACK) wq32  = (const int*)d_in[i];
        else if (s == (long long)T_DIM)         sx    = (const float*)d_in[i];
        else if (s == (long long)N_DIM)         ws    = (const float*)d_in[i];
    }
    if (!pqx32 || !wq32 || !sx || !ws) {
        pqx32 = (const int*)d_in[0];
        sx    = (const float*)d_in[1];
        wq32  = (const int*)d_in[2];
        ws    = (const float*)d_in[3];
    }
    float* out = (float*)d_out;

    __half* a_dev = nullptr;
    __half* w_dev = nullptr;
    cudaGetSymbolAddress((void**)&a_dev, g_a);
    cudaGetSymbolAddress((void**)&w_dev, g_w);

    // Prologue: int4 (delivered as int32) -> planar fp16, once per element.
    const int n4_a = (T_DIM * KPACK) / 4;
    const int n4_b = (N_DIM * KPACK) / 4;
    repack_fp16_kernel<<<n4_a / 256, 256>>>(pqx32, (unsigned*)a_dev, n4_a);
    repack_fp16_kernel<<<n4_b / 256, 256>>>(wq32,  (unsigned*)w_dev, n4_b);

    cudaFuncSetAttribute(gemm_hmma16_pipe_kernel,
                         cudaFuncAttributeMaxDynamicSharedMemorySize,
                         SMEM_WORDS * 4);
    dim3 grid(N_DIM / BN, T_DIM / BM);   // 86 x 32
    gemm_hmma16_pipe_kernel<<<grid, THREADS, SMEM_WORDS * 4>>>(a_dev, sx, w_dev, ws, out);
}